// round 5
// baseline (speedup 1.0000x reference)
#include <cuda_runtime.h>
#include <cuda_bf16.h>
#include <cstdint>

#define D     128
#define NA    16384
#define NC    16384
#define NE    524288
#define TR    64
#define NT    256
#define KC    16
#define TRE   64      // edges per block (4 row-groups x 2 col-halves = 8 warps)
#define EPS   1e-5f

// ---------------------------------------------------------------------------
// device scratch (no allocation)
// ---------------------------------------------------------------------------
__device__ __align__(16) float g_qb[NA * D];    // relu(GN(agts@query_w)) @ ctx_w1[128:256]
__device__ __align__(16) float g_ctxc[NC * D];  // ctx @ ctx_w1[256:384]
__device__ __align__(16) float g_acc[NA * D];   // agts@agt_w + scattered edge output
__device__ __align__(16) uint4 g_wh[3 * 2048];  // pre-split bf16-hi W images (smem layout)
__device__ __align__(16) uint4 g_wl[3 * 2048];  // pre-split bf16-lo W images

// ---------------------------------------------------------------------------
// helpers
// ---------------------------------------------------------------------------
__device__ __forceinline__ uint32_t smem_u32(const void* p) {
    uint32_t a;
    asm("{ .reg .u64 t; cvta.to.shared.u64 t, %1; cvt.u32.u64 %0, t; }" : "=r"(a) : "l"(p));
    return a;
}

__device__ __forceinline__ void mma16816(float c[4], const uint32_t a[4], const uint32_t b[2]) {
    asm volatile(
        "mma.sync.aligned.m16n8k16.row.col.f32.bf16.bf16.f32 "
        "{%0,%1,%2,%3}, {%4,%5,%6,%7}, {%8,%9}, {%0,%1,%2,%3};"
        : "+f"(c[0]), "+f"(c[1]), "+f"(c[2]), "+f"(c[3])
        : "r"(a[0]), "r"(a[1]), "r"(a[2]), "r"(a[3]), "r"(b[0]), "r"(b[1]));
}

__device__ __forceinline__ void ldsm_x4_t(uint32_t r[4], uint32_t addr) {
    asm volatile("ldmatrix.sync.aligned.m8n8.x4.trans.shared.b16 {%0,%1,%2,%3}, [%4];"
                 : "=r"(r[0]), "=r"(r[1]), "=r"(r[2]), "=r"(r[3]) : "r"(addr));
}

__device__ __forceinline__ void ldsm_x4(uint32_t r[4], uint32_t addr) {
    asm volatile("ldmatrix.sync.aligned.m8n8.x4.shared.b16 {%0,%1,%2,%3}, [%4];"
                 : "=r"(r[0]), "=r"(r[1]), "=r"(r[2]), "=r"(r[3]) : "r"(addr));
}

__device__ __forceinline__ void stsm_x4(uint32_t addr, const uint32_t r[4]) {
    asm volatile("stmatrix.sync.aligned.m8n8.x4.shared.b16 [%0], {%1,%2,%3,%4};"
                 :: "r"(addr), "r"(r[0]), "r"(r[1]), "r"(r[2]), "r"(r[3]) : "memory");
}

__device__ __forceinline__ void red4(float* p, float a, float b, float c, float d) {
    asm volatile("red.global.add.v4.f32 [%0], {%1,%2,%3,%4};"
                 :: "l"(p), "f"(a), "f"(b), "f"(c), "f"(d) : "memory");
}

__device__ __forceinline__ void split_pack(float x0, float x1, uint32_t& hp, uint32_t& lp) {
    __nv_bfloat16 h0 = __float2bfloat16(x0);
    __nv_bfloat16 h1 = __float2bfloat16(x1);
    float r0 = x0 - __bfloat162float(h0);
    float r1 = x1 - __bfloat162float(h1);
    __nv_bfloat16 l0 = __float2bfloat16(r0);
    __nv_bfloat16 l1 = __float2bfloat16(r1);
    hp = (uint32_t)__bfloat16_as_ushort(h0) | ((uint32_t)__bfloat16_as_ushort(h1) << 16);
    lp = (uint32_t)__bfloat16_as_ushort(l0) | ((uint32_t)__bfloat16_as_ushort(l1) << 16);
}

// ---------------------------------------------------------------------------
// k_edge smem map (bytes).  W region [0,64K) is time-shared with the A
// exchange (Aex-hi [0,16K), Aex-lo [16K,32K)) between stages.
// ---------------------------------------------------------------------------
#define SM_W      0
#define SM_AEXH   0
#define SM_AEXL   16384
#define SM_STATS  65536   /* 256 floats: [half][sum/sq][64 rows] */
#define SM_HIS    66560
#define SM_WIS    66816
#define SM_D2     67072
#define SMEM_EDGE 67584

// W smem layout: k row = 256B (16 groups of 16B), group nt at k*256 + ((nt ^ (k&7))<<4)
__global__ void k_prep(const float* __restrict__ w0, const float* __restrict__ w1,
                       const float* __restrict__ w2) {
    int m = blockIdx.y;
    const float* src = (m == 0) ? w0 : (m == 1 ? w1 : w2);
    int gidx = blockIdx.x * 256 + threadIdx.x;       // 0..4095 float4s
    int k = gidx >> 5, nq = gidx & 31;
    float4 v = ((const float4*)src)[gidx];
    uint32_t h01, l01, h23, l23;
    split_pack(v.x, v.y, h01, l01);
    split_pack(v.z, v.w, h23, l23);
    uint32_t off = (uint32_t)(k * 256 + (((nq >> 1) ^ (k & 7)) << 4) + (nq & 1) * 8);
    *(uint2*)((char*)g_wh + m * 32768 + off) = make_uint2(h01, h23);
    *(uint2*)((char*)g_wl + m * 32768 + off) = make_uint2(l01, l23);
}

__device__ __forceinline__ void copy_w(int m, char* smem, int tid) {
    const uint4* sh = g_wh + m * 2048;
    const uint4* sl = g_wl + m * 2048;
    uint4* dh = (uint4*)(smem + SM_W);
    uint4* dl = (uint4*)(smem + SM_W + 32768);
#pragma unroll
    for (int i = 0; i < 8; i++) {
        dh[i * 256 + tid] = sh[i * 256 + tid];
        dl[i * 256 + tid] = sl[i * 256 + tid];
    }
}

// A-exchange addressing: row-major 64 rows x 256B, XOR swizzle on 16B groups
__device__ __forceinline__ uint32_t aex_addr(uint32_t sb, int hil, int row, int g) {
    return sb + (uint32_t)(hil ? SM_AEXL : SM_AEXH) +
           (uint32_t)(row * 256 + ((g ^ (row & 7)) << 4));
}

// per-lane (row, g-base) for ld/st-matrix x4 at chunk kc, row group rg
__device__ __forceinline__ void aex_lane(int rg, int l, int& row, int& gsel) {
    int sel = l >> 3;
    row = rg * 16 + (sel & 1) * 8 + (l & 7);
    gsel = sel >> 1;   // + 2*kc
}

// C[8 tiles][4] += A(hi/lo) @ W(hi/lo), 3-product split; warp covers cols nh*64..+63
__device__ __forceinline__ void mma_stage(float c[8][4],
                                          const uint32_t ahi[8][4], const uint32_t alo[8][4],
                                          uint32_t sb, int l, int nh) {
    const int kk   = ((l >> 3) & 1) * 8 + (l & 7);
    const int sxr  = kk & 7;
    const int nadd = l >> 4;
    const uint32_t rowbase = sb + SM_W + (uint32_t)(kk * 256);
#pragma unroll
    for (int kc = 0; kc < 8; kc++) {
        uint32_t base = rowbase + (uint32_t)(kc * 4096);
#pragma unroll
        for (int p = 0; p < 4; p++) {
            int ntx = nh * 8 + 2 * p + nadd;
            uint32_t b4[4];
            ldsm_x4_t(b4, base + (uint32_t)((ntx ^ sxr) << 4));          // W_hi
            mma16816(c[2 * p],     ahi[kc], b4);
            mma16816(c[2 * p + 1], ahi[kc], b4 + 2);
            mma16816(c[2 * p],     alo[kc], b4);
            mma16816(c[2 * p + 1], alo[kc], b4 + 2);
        }
#pragma unroll
        for (int p = 0; p < 4; p++) {
            int ntx = nh * 8 + 2 * p + nadd;
            uint32_t b4[4];
            ldsm_x4_t(b4, base + 32768u + (uint32_t)((ntx ^ sxr) << 4)); // W_lo
            mma16816(c[2 * p],     ahi[kc], b4);
            mma16816(c[2 * p + 1], ahi[kc], b4 + 2);
        }
    }
}

// GN(+relu) epilogue with cross-half stats, write Aex, rebuild A frags.
// Ends with all barriers needed before the next W copy.
template <bool GATHER>
__device__ __forceinline__ void ep_gn(float c[8][4],
                                      uint32_t ahi[8][4], uint32_t alo[8][4],
                                      const float* __restrict__ gamma,
                                      const float* __restrict__ beta,
                                      uint32_t sb, char* smem,
                                      const int* hi_s, const int* wi_s,
                                      int rg, int nh, int l) {
    const int q = l & 3;
    const int rA = rg * 16 + (l >> 2);   // block-local rows
    const int rB = rA + 8;
    const int cb = nh * 64;

    if (GATHER) {
        const float* qA = g_qb   + hi_s[rA] * D + cb;
        const float* qB = g_qb   + hi_s[rB] * D + cb;
        const float* cA = g_ctxc + wi_s[rA] * D + cb;
        const float* cB = g_ctxc + wi_s[rB] * D + cb;
#pragma unroll
        for (int t = 0; t < 8; t++) {
            int c0 = t * 8 + q * 2;
            float2 a1 = __ldg((const float2*)(qA + c0));
            float2 a2 = __ldg((const float2*)(cA + c0));
            float2 b1 = __ldg((const float2*)(qB + c0));
            float2 b2 = __ldg((const float2*)(cB + c0));
            c[t][0] += a1.x + a2.x;  c[t][1] += a1.y + a2.y;
            c[t][2] += b1.x + b2.x;  c[t][3] += b1.y + b2.y;
        }
    }
    // half-row stats
    float sA = 0.f, qsA = 0.f, sB = 0.f, qsB = 0.f;
#pragma unroll
    for (int t = 0; t < 8; t++) {
        sA += c[t][0] + c[t][1];
        qsA = fmaf(c[t][0], c[t][0], fmaf(c[t][1], c[t][1], qsA));
        sB += c[t][2] + c[t][3];
        qsB = fmaf(c[t][2], c[t][2], fmaf(c[t][3], c[t][3], qsB));
    }
    sA  += __shfl_xor_sync(~0u, sA, 1);  sA  += __shfl_xor_sync(~0u, sA, 2);
    qsA += __shfl_xor_sync(~0u, qsA, 1); qsA += __shfl_xor_sync(~0u, qsA, 2);
    sB  += __shfl_xor_sync(~0u, sB, 1);  sB  += __shfl_xor_sync(~0u, sB, 2);
    qsB += __shfl_xor_sync(~0u, qsB, 1); qsB += __shfl_xor_sync(~0u, qsB, 2);

    float* st = (float*)(smem + SM_STATS);   // [half][sum(64) | sq(64)]
    if (q == 0) {
        st[nh * 128 + rA]      = sA;  st[nh * 128 + 64 + rA] = qsA;
        st[nh * 128 + rB]      = sB;  st[nh * 128 + 64 + rB] = qsB;
    }
    __syncthreads();   // stats visible; all W-hi reads done -> Aex overwrite safe

    float S   = st[rA] + st[128 + rA];
    float SQ  = st[64 + rA] + st[192 + rA];
    float Sb  = st[rB] + st[128 + rB];
    float SQb = st[64 + rB] + st[192 + rB];
    float mA = S  * (1.f / 128.f), vA = SQ  * (1.f / 128.f) - mA * mA, rsA = rsqrtf(vA + EPS);
    float mB = Sb * (1.f / 128.f), vB = SQb * (1.f / 128.f) - mB * mB, rsB = rsqrtf(vB + EPS);

    int row, gsel;
    aex_lane(rg, l, row, gsel);
#pragma unroll
    for (int u = 0; u < 4; u++) {
        uint32_t dhi[4], dlo[4];
#pragma unroll
        for (int tt = 0; tt < 2; tt++) {
            int t = 2 * u + tt;
            int c0 = cb + t * 8 + q * 2;
            float g0 = __ldg(gamma + c0), g1 = __ldg(gamma + c0 + 1);
            float b0 = __ldg(beta + c0),  b1 = __ldg(beta + c0 + 1);
            float xA0 = fmaxf(fmaf((c[t][0] - mA) * rsA, g0, b0), 0.f);
            float xA1 = fmaxf(fmaf((c[t][1] - mA) * rsA, g1, b1), 0.f);
            float xB0 = fmaxf(fmaf((c[t][2] - mB) * rsB, g0, b0), 0.f);
            float xB1 = fmaxf(fmaf((c[t][3] - mB) * rsB, g1, b1), 0.f);
            split_pack(xA0, xA1, dhi[tt * 2],     dlo[tt * 2]);
            split_pack(xB0, xB1, dhi[tt * 2 + 1], dlo[tt * 2 + 1]);
        }
        int kc = nh * 4 + u;
        int g = 2 * kc + gsel;
        stsm_x4(aex_addr(sb, 0, row, g), dhi);
        stsm_x4(aex_addr(sb, 1, row, g), dlo);
    }
    __syncthreads();   // Aex visible

#pragma unroll
    for (int kc = 0; kc < 8; kc++) {
        int g = 2 * kc + gsel;
        ldsm_x4(ahi[kc], aex_addr(sb, 0, row, g));
        ldsm_x4(alo[kc], aex_addr(sb, 1, row, g));
    }
    __syncthreads();   // Aex reads done -> next W copy safe
}

__global__ __launch_bounds__(256, 2) void k_edge_mma(
    const float* __restrict__ agt_ctrs, const float* __restrict__ ctx_ctrs,
    const int* __restrict__ hi, const int* __restrict__ wi,
    const float* __restrict__ dist_w1, const float* __restrict__ dist_b1,
    const float* __restrict__ dist_g2, const float* __restrict__ dist_b2,
    const float* __restrict__ ctx_g1, const float* __restrict__ ctx_b1) {
    extern __shared__ char smem[];
    const uint32_t sb = smem_u32(smem);
    const int tid = threadIdx.x;
    const int w = tid >> 5, l = tid & 31, q = l & 3;
    const int rg = w >> 1, nh = w & 1;         // row group 0-3, col half 0-1
    const int rA = rg * 16 + (l >> 2);         // block-local rows owned by lane
    const int rB = rA + 8;

    int* hi_s = (int*)(smem + SM_HIS);
    int* wi_s = (int*)(smem + SM_WIS);
    float2* d2s = (float2*)(smem + SM_D2);
    const int e0 = blockIdx.x * TRE;
    if (tid < TRE) {
        int h = hi[e0 + tid], ww = wi[e0 + tid];
        hi_s[tid] = h; wi_s[tid] = ww;
        float2 ac = ((const float2*)agt_ctrs)[h];
        float2 cc = ((const float2*)ctx_ctrs)[ww];
        d2s[tid] = make_float2(ac.x - cc.x, ac.y - cc.y);
    }
    copy_w(0, smem, tid);
    __syncthreads();

    // initial A = relu(d2 @ dist_w1 + b1) in fragment layout (all 8 kc; pair-duplicated)
    uint32_t ahi[8][4], alo[8][4];
    {
        float2 ddA = d2s[rA], ddB = d2s[rB];
#pragma unroll
        for (int kc = 0; kc < 8; kc++) {
#pragma unroll
            for (int h = 0; h < 2; h++) {
                int col = kc * 16 + h * 8 + q * 2;
                float w00 = __ldg(dist_w1 + col),     w01 = __ldg(dist_w1 + col + 1);
                float w10 = __ldg(dist_w1 + D + col), w11 = __ldg(dist_w1 + D + col + 1);
                float bb0 = __ldg(dist_b1 + col),     bb1 = __ldg(dist_b1 + col + 1);
                float xA0 = fmaxf(fmaf(ddA.x, w00, fmaf(ddA.y, w10, bb0)), 0.f);
                float xA1 = fmaxf(fmaf(ddA.x, w01, fmaf(ddA.y, w11, bb1)), 0.f);
                float xB0 = fmaxf(fmaf(ddB.x, w00, fmaf(ddB.y, w10, bb0)), 0.f);
                float xB1 = fmaxf(fmaf(ddB.x, w01, fmaf(ddB.y, w11, bb1)), 0.f);
                split_pack(xA0, xA1, ahi[kc][h * 2],     alo[kc][h * 2]);
                split_pack(xB0, xB1, ahi[kc][h * 2 + 1], alo[kc][h * 2 + 1]);
            }
        }
    }

    float c[8][4];
    // ---- stage 1: @ dist_w2, GN(dist_g2,b2)+relu ----
#pragma unroll
    for (int t = 0; t < 8; t++) { c[t][0] = c[t][1] = c[t][2] = c[t][3] = 0.f; }
    mma_stage(c, ahi, alo, sb, l, nh);
    ep_gn<false>(c, ahi, alo, dist_g2, dist_b2, sb, smem, hi_s, wi_s, rg, nh, l);

    // ---- stage 2: @ ctx_w1[0:128] + qb[hi] + ctxc[wi], GN(ctx_g1,b1)+relu ----
    copy_w(1, smem, tid);
    __syncthreads();
#pragma unroll
    for (int t = 0; t < 8; t++) { c[t][0] = c[t][1] = c[t][2] = c[t][3] = 0.f; }
    mma_stage(c, ahi, alo, sb, l, nh);
    ep_gn<true>(c, ahi, alo, ctx_g1, ctx_b1, sb, smem, hi_s, wi_s, rg, nh, l);

    // ---- stage 3: @ ctx_w2, scatter-add ----
    copy_w(2, smem, tid);
    __syncthreads();
#pragma unroll
    for (int t = 0; t < 8; t++) { c[t][0] = c[t][1] = c[t][2] = c[t][3] = 0.f; }
    mma_stage(c, ahi, alo, sb, l, nh);
    {
        float* baseA = g_acc + hi_s[rA] * D + nh * 64;
        float* baseB = g_acc + hi_s[rB] * D + nh * 64;
        const bool even = (q & 1) == 0;
#pragma unroll
        for (int t = 0; t < 8; t++) {
            float x0 = __shfl_xor_sync(~0u, c[t][0], 1);
            float x1 = __shfl_xor_sync(~0u, c[t][1], 1);
            float x2 = __shfl_xor_sync(~0u, c[t][2], 1);
            float x3 = __shfl_xor_sync(~0u, c[t][3], 1);
            if (even) red4(baseA + t * 8 + q * 2,       c[t][0], c[t][1], x0, x1);
            else      red4(baseB + t * 8 + (q - 1) * 2, x2, x3, c[t][2], c[t][3]);
        }
    }
}

// ---------------------------------------------------------------------------
// FFMA node kernels (known good)
// ---------------------------------------------------------------------------
__device__ __forceinline__ void gemm_tile(const float* in_s, const float* __restrict__ W,
                                          float* wbuf, float acc[8][4], int e0, int c4, int tid) {
    const float4* Wg = reinterpret_cast<const float4*>(W);
    float4* wb = reinterpret_cast<float4*>(wbuf);
    for (int kb = 0; kb < D; kb += KC) {
        __syncthreads();
        wb[tid]      = Wg[kb * (D / 4) + tid];
        wb[tid + NT] = Wg[kb * (D / 4) + tid + NT];
        __syncthreads();
#pragma unroll
        for (int kk = 0; kk < KC; kk++) {
            float4 w = wb[kk * (D / 4) + c4];
#pragma unroll
            for (int i = 0; i < 8; i++) {
                float h = in_s[(e0 + i) * D + kb + kk];
                acc[i][0] = fmaf(h, w.x, acc[i][0]);
                acc[i][1] = fmaf(h, w.y, acc[i][1]);
                acc[i][2] = fmaf(h, w.z, acc[i][2]);
                acc[i][3] = fmaf(h, w.w, acc[i][3]);
            }
        }
    }
}

__device__ __forceinline__ void zero_acc(float acc[8][4]) {
#pragma unroll
    for (int i = 0; i < 8; i++)
#pragma unroll
        for (int j = 0; j < 4; j++) acc[i][j] = 0.f;
}

__device__ __forceinline__ void store_acc(float* io, const float acc[8][4], int e0, int c4) {
#pragma unroll
    for (int i = 0; i < 8; i++) {
        float4 v = make_float4(acc[i][0], acc[i][1], acc[i][2], acc[i][3]);
        *reinterpret_cast<float4*>(&io[(e0 + i) * D + c4 * 4]) = v;
    }
}

__device__ __forceinline__ void gn_rows(float* io, const float* __restrict__ g,
                                        const float* __restrict__ b, bool do_relu, int tid) {
    int lane = tid & 31, w = tid >> 5;
    for (int r = w; r < TR; r += 8) {
        float v[4], s = 0.f, sq = 0.f;
#pragma unroll
        for (int j = 0; j < 4; j++) {
            v[j] = io[r * D + lane + 32 * j];
            s += v[j]; sq += v[j] * v[j];
        }
#pragma unroll
        for (int o = 16; o > 0; o >>= 1) {
            s  += __shfl_xor_sync(0xffffffffu, s, o);
            sq += __shfl_xor_sync(0xffffffffu, sq, o);
        }
        float mean = s * (1.f / D);
        float var  = sq * (1.f / D) - mean * mean;
        float rstd = rsqrtf(var + EPS);
#pragma unroll
        for (int j = 0; j < 4; j++) {
            int c = lane + 32 * j;
            float x = (v[j] - mean) * rstd * g[c] + b[c];
            io[r * D + c] = do_relu ? fmaxf(x, 0.f) : x;
        }
    }
}

__global__ __launch_bounds__(NT) void k_qb(const float* __restrict__ agts,
                                           const float* __restrict__ query_w,
                                           const float* __restrict__ query_g,
                                           const float* __restrict__ query_b,
                                           const float* __restrict__ ctx_w1) {
    __shared__ float io[TR * D];
    __shared__ float wbuf[KC * D];
    int tid = threadIdx.x;
    int r0 = blockIdx.x * TR;
    int lane = tid & 31, wid = tid >> 5;
    int c4 = lane, e0 = wid * 8;

    for (int idx = tid; idx < TR * D; idx += NT) io[idx] = agts[r0 * D + idx];

    float acc[8][4];
    zero_acc(acc);
    gemm_tile(io, query_w, wbuf, acc, e0, c4, tid);
    __syncthreads();
    store_acc(io, acc, e0, c4);
    __syncthreads();
    gn_rows(io, query_g, query_b, true, tid);
    __syncthreads();

    zero_acc(acc);
    gemm_tile(io, ctx_w1 + D * D, wbuf, acc, e0, c4, tid);
#pragma unroll
    for (int i = 0; i < 8; i++) {
        float4 v = make_float4(acc[i][0], acc[i][1], acc[i][2], acc[i][3]);
        *reinterpret_cast<float4*>(&g_qb[(r0 + e0 + i) * D + c4 * 4]) = v;
    }
}

__global__ __launch_bounds__(NT) void k_accinit(const float* __restrict__ agts,
                                                const float* __restrict__ agt_w) {
    __shared__ float io[TR * D];
    __shared__ float wbuf[KC * D];
    int tid = threadIdx.x;
    int r0 = blockIdx.x * TR;
    int lane = tid & 31, wid = tid >> 5;
    int c4 = lane, e0 = wid * 8;

    for (int idx = tid; idx < TR * D; idx += NT) io[idx] = agts[r0 * D + idx];

    float acc[8][4];
    zero_acc(acc);
    gemm_tile(io, agt_w, wbuf, acc, e0, c4, tid);
#pragma unroll
    for (int i = 0; i < 8; i++) {
        float4 v = make_float4(acc[i][0], acc[i][1], acc[i][2], acc[i][3]);
        *reinterpret_cast<float4*>(&g_acc[(r0 + e0 + i) * D + c4 * 4]) = v;
    }
}

__global__ __launch_bounds__(NT) void k_ctxc(const float* __restrict__ ctx,
                                             const float* __restrict__ ctx_w1) {
    __shared__ float io[TR * D];
    __shared__ float wbuf[KC * D];
    int tid = threadIdx.x;
    int r0 = blockIdx.x * TR;
    int lane = tid & 31, wid = tid >> 5;
    int c4 = lane, e0 = wid * 8;

    for (int idx = tid; idx < TR * D; idx += NT) io[idx] = ctx[r0 * D + idx];

    float acc[8][4];
    zero_acc(acc);
    gemm_tile(io, ctx_w1 + 2 * D * D, wbuf, acc, e0, c4, tid);
#pragma unroll
    for (int i = 0; i < 8; i++) {
        float4 v = make_float4(acc[i][0], acc[i][1], acc[i][2], acc[i][3]);
        *reinterpret_cast<float4*>(&g_ctxc[(r0 + e0 + i) * D + c4 * 4]) = v;
    }
}

__global__ __launch_bounds__(NT) void k_final(const float* __restrict__ agts,
                                              const float* __restrict__ norm_g,
                                              const float* __restrict__ norm_b,
                                              const float* __restrict__ lin_w,
                                              const float* __restrict__ lin_g,
                                              const float* __restrict__ lin_b,
                                              float* __restrict__ out) {
    __shared__ float io[TR * D];
    __shared__ float wbuf[KC * D];
    int tid = threadIdx.x;
    int r0 = blockIdx.x * TR;
    int lane = tid & 31, wid = tid >> 5;
    int c4 = lane, e0 = wid * 8;

    for (int idx = tid; idx < TR * D; idx += NT) io[idx] = g_acc[r0 * D + idx];
    __syncthreads();
    gn_rows(io, norm_g, norm_b, true, tid);
    __syncthreads();

    float acc[8][4];
    zero_acc(acc);
    gemm_tile(io, lin_w, wbuf, acc, e0, c4, tid);
    __syncthreads();
    store_acc(io, acc, e0, c4);
    __syncthreads();

    for (int r = wid; r < TR; r += 8) {
        float v[4], s = 0.f, sq = 0.f;
#pragma unroll
        for (int j = 0; j < 4; j++) {
            v[j] = io[r * D + lane + 32 * j];
            s += v[j]; sq += v[j] * v[j];
        }
#pragma unroll
        for (int o = 16; o > 0; o >>= 1) {
            s  += __shfl_xor_sync(0xffffffffu, s, o);
            sq += __shfl_xor_sync(0xffffffffu, sq, o);
        }
        float mean = s * (1.f / D);
        float var  = sq * (1.f / D) - mean * mean;
        float rstd = rsqrtf(var + EPS);
#pragma unroll
        for (int j = 0; j < 4; j++) {
            int c = lane + 32 * j;
            float x = (v[j] - mean) * rstd * lin_g[c] + lin_b[c];
            float res = agts[(r0 + r) * D + c];
            out[(r0 + r) * D + c] = fmaxf(x + res, 0.f);
        }
    }
}

// ---------------------------------------------------------------------------
extern "C" void kernel_launch(void* const* d_in, const int* in_sizes, int n_in,
                              void* d_out, int out_size) {
    const float* agts     = (const float*)d_in[0];
    const float* ctx      = (const float*)d_in[1];
    const float* agt_ctrs = (const float*)d_in[2];
    const float* ctx_ctrs = (const float*)d_in[3];
    const int*   hi       = (const int*)d_in[4];
    const int*   wi       = (const int*)d_in[5];
    const float* dist_w1  = (const float*)d_in[6];
    const float* dist_b1  = (const float*)d_in[7];
    const float* dist_w2  = (const float*)d_in[8];
    const float* dist_g2  = (const float*)d_in[9];
    const float* dist_b2  = (const float*)d_in[10];
    const float* query_w  = (const float*)d_in[11];
    const float* query_g  = (const float*)d_in[12];
    const float* query_b  = (const float*)d_in[13];
    const float* ctx_w1   = (const float*)d_in[14];
    const float* ctx_g1   = (const float*)d_in[15];
    const float* ctx_b1   = (const float*)d_in[16];
    const float* ctx_w2   = (const float*)d_in[17];
    const float* agt_w    = (const float*)d_in[18];
    const float* norm_g   = (const float*)d_in[19];
    const float* norm_b   = (const float*)d_in[20];
    const float* lin_w    = (const float*)d_in[21];
    const float* lin_g    = (const float*)d_in[22];
    const float* lin_b    = (const float*)d_in[23];
    float* out = (float*)d_out;

    cudaFuncSetAttribute(k_edge_mma, cudaFuncAttributeMaxDynamicSharedMemorySize, SMEM_EDGE);

    k_prep<<<dim3(16, 3), 256>>>(dist_w2, ctx_w1, ctx_w2);
    k_qb<<<NA / TR, NT>>>(agts, query_w, query_g, query_b, ctx_w1);
    k_accinit<<<NA / TR, NT>>>(agts, agt_w);
    k_ctxc<<<NC / TR, NT>>>(ctx, ctx_w1);
    k_edge_mma<<<NE / TRE, 256, SMEM_EDGE>>>(agt_ctrs, ctx_ctrs, hi, wi,
                                             dist_w1, dist_b1,
                                             dist_g2, dist_b2,
                                             ctx_g1, ctx_b1);
    k_final<<<NA / TR, NT>>>(agts, norm_g, norm_b, lin_w, lin_g, lin_b, out);
}

// round 6
// speedup vs baseline: 1.1244x; 1.1244x over previous
#include <cuda_runtime.h>
#include <cuda_bf16.h>
#include <cstdint>

#define D     128
#define NA    16384
#define NC    16384
#define NE    524288
#define TR    64
#define NT    256
#define KC    16
#define TRE   64      // edges per block (4 row-groups x 2 col-halves = 8 warps)
#define EPS   1e-5f

// ---------------------------------------------------------------------------
// device scratch (no allocation)
// ---------------------------------------------------------------------------
__device__ __align__(16) float g_qb[NA * D];    // relu(GN(agts@query_w)) @ ctx_w1[128:256]
__device__ __align__(16) float g_ctxc[NC * D];  // ctx @ ctx_w1[256:384]
__device__ __align__(16) float g_acc[NA * D];   // agts@agt_w + scattered edge output
__device__ __align__(16) uint4 g_wh[3 * 2048];  // pre-split bf16-hi W images (smem layout)
__device__ __align__(16) uint4 g_wl[3 * 2048];  // pre-split bf16-lo W images

// ---------------------------------------------------------------------------
// helpers
// ---------------------------------------------------------------------------
__device__ __forceinline__ uint32_t smem_u32(const void* p) {
    uint32_t a;
    asm("{ .reg .u64 t; cvta.to.shared.u64 t, %1; cvt.u32.u64 %0, t; }" : "=r"(a) : "l"(p));
    return a;
}

__device__ __forceinline__ void mma16816(float c[4], const uint32_t a[4], const uint32_t b[2]) {
    asm volatile(
        "mma.sync.aligned.m16n8k16.row.col.f32.bf16.bf16.f32 "
        "{%0,%1,%2,%3}, {%4,%5,%6,%7}, {%8,%9}, {%0,%1,%2,%3};"
        : "+f"(c[0]), "+f"(c[1]), "+f"(c[2]), "+f"(c[3])
        : "r"(a[0]), "r"(a[1]), "r"(a[2]), "r"(a[3]), "r"(b[0]), "r"(b[1]));
}

__device__ __forceinline__ void ldsm_x4_t(uint32_t r[4], uint32_t addr) {
    asm volatile("ldmatrix.sync.aligned.m8n8.x4.trans.shared.b16 {%0,%1,%2,%3}, [%4];"
                 : "=r"(r[0]), "=r"(r[1]), "=r"(r[2]), "=r"(r[3]) : "r"(addr));
}

__device__ __forceinline__ void ldsm_x4(uint32_t r[4], uint32_t addr) {
    asm volatile("ldmatrix.sync.aligned.m8n8.x4.shared.b16 {%0,%1,%2,%3}, [%4];"
                 : "=r"(r[0]), "=r"(r[1]), "=r"(r[2]), "=r"(r[3]) : "r"(addr));
}

__device__ __forceinline__ void stsm_x4(uint32_t addr, const uint32_t r[4]) {
    asm volatile("stmatrix.sync.aligned.m8n8.x4.shared.b16 [%0], {%1,%2,%3,%4};"
                 :: "r"(addr), "r"(r[0]), "r"(r[1]), "r"(r[2]), "r"(r[3]) : "memory");
}

__device__ __forceinline__ void red4(float* p, float a, float b, float c, float d) {
    asm volatile("red.global.add.v4.f32 [%0], {%1,%2,%3,%4};"
                 :: "l"(p), "f"(a), "f"(b), "f"(c), "f"(d) : "memory");
}

__device__ __forceinline__ void cp16(uint32_t daddr, const void* g) {
    asm volatile("cp.async.cg.shared.global [%0], [%1], 16;" :: "r"(daddr), "l"(g) : "memory");
}
__device__ __forceinline__ void cp_commit() { asm volatile("cp.async.commit_group;" ::: "memory"); }
__device__ __forceinline__ void cp_wait0()  { asm volatile("cp.async.wait_group 0;" ::: "memory"); }

__device__ __forceinline__ void split_pack(float x0, float x1, uint32_t& hp, uint32_t& lp) {
    __nv_bfloat16 h0 = __float2bfloat16(x0);
    __nv_bfloat16 h1 = __float2bfloat16(x1);
    float r0 = x0 - __bfloat162float(h0);
    float r1 = x1 - __bfloat162float(h1);
    __nv_bfloat16 l0 = __float2bfloat16(r0);
    __nv_bfloat16 l1 = __float2bfloat16(r1);
    hp = (uint32_t)__bfloat16_as_ushort(h0) | ((uint32_t)__bfloat16_as_ushort(h1) << 16);
    lp = (uint32_t)__bfloat16_as_ushort(l0) | ((uint32_t)__bfloat16_as_ushort(l1) << 16);
}

// ---------------------------------------------------------------------------
// k_edge smem map (bytes). W and Aex are now SEPARATE regions (no time share).
// ---------------------------------------------------------------------------
#define SM_W      0        /* hi 32K @0, lo 32K @32768 */
#define SM_AEXH   65536    /* 16K */
#define SM_AEXL   81920    /* 16K */
#define SM_STATS  98304    /* 256 floats */
#define SM_HIS    99328
#define SM_WIS    99584
#define SM_D2     99840
#define SMEM_EDGE 100352

// W smem layout: k row = 256B (16 groups of 16B), group nt at k*256 + ((nt ^ (k&7))<<4)
__global__ void k_prep(const float* __restrict__ w0, const float* __restrict__ w1,
                       const float* __restrict__ w2) {
    int m = blockIdx.y;
    const float* src = (m == 0) ? w0 : (m == 1 ? w1 : w2);
    int gidx = blockIdx.x * 256 + threadIdx.x;       // 0..4095 float4s
    int k = gidx >> 5, nq = gidx & 31;
    float4 v = ((const float4*)src)[gidx];
    uint32_t h01, l01, h23, l23;
    split_pack(v.x, v.y, h01, l01);
    split_pack(v.z, v.w, h23, l23);
    uint32_t off = (uint32_t)(k * 256 + (((nq >> 1) ^ (k & 7)) << 4) + (nq & 1) * 8);
    *(uint2*)((char*)g_wh + m * 32768 + off) = make_uint2(h01, h23);
    *(uint2*)((char*)g_wl + m * 32768 + off) = make_uint2(l01, l23);
}

// async copy W image m into smem W region (16 x 16B per thread)
__device__ __forceinline__ void copy_w_async(int m, uint32_t sb, int tid) {
    const uint4* sh = g_wh + m * 2048;
    const uint4* sl = g_wl + m * 2048;
#pragma unroll
    for (int i = 0; i < 8; i++) {
        cp16(sb + SM_W + (uint32_t)((i * 256 + tid) * 16),          sh + i * 256 + tid);
        cp16(sb + SM_W + 32768u + (uint32_t)((i * 256 + tid) * 16), sl + i * 256 + tid);
    }
    cp_commit();
}

// A-exchange addressing: 64 rows x 256B, XOR swizzle on 16B groups
__device__ __forceinline__ uint32_t aex_addr(uint32_t sb, int hil, int row, int g) {
    return sb + (uint32_t)(hil ? SM_AEXL : SM_AEXH) +
           (uint32_t)(row * 256 + ((g ^ (row & 7)) << 4));
}

// per-lane (row, g-base) for ld/st-matrix x4 tiles, row group rg
__device__ __forceinline__ void aex_lane(int rg, int l, int& row, int& gsel) {
    int sel = l >> 3;
    row = rg * 16 + (sel & 1) * 8 + (l & 7);
    gsel = sel >> 1;   // + 2*kc
}

// C[8 tiles][4] += A(hi/lo from Aex smem) @ W(hi/lo), 3-product split
__device__ __forceinline__ void mma_stage(float c[8][4], uint32_t sb, int rg, int nh, int l) {
    const int kk   = ((l >> 3) & 1) * 8 + (l & 7);
    const int sxr  = kk & 7;
    const int nadd = l >> 4;
    const uint32_t rowbase = sb + SM_W + (uint32_t)(kk * 256);
    int arow, gsel;
    aex_lane(rg, l, arow, gsel);
#pragma unroll
    for (int kc = 0; kc < 8; kc++) {
        uint32_t ahi[4], alo[4];
        ldsm_x4(ahi, aex_addr(sb, 0, arow, 2 * kc + gsel));
        ldsm_x4(alo, aex_addr(sb, 1, arow, 2 * kc + gsel));
        uint32_t base = rowbase + (uint32_t)(kc * 4096);
#pragma unroll
        for (int p = 0; p < 4; p++) {
            int ntx = nh * 8 + 2 * p + nadd;
            uint32_t b4[4];
            ldsm_x4_t(b4, base + (uint32_t)((ntx ^ sxr) << 4));          // W_hi
            mma16816(c[2 * p],     ahi, b4);
            mma16816(c[2 * p + 1], ahi, b4 + 2);
            mma16816(c[2 * p],     alo, b4);
            mma16816(c[2 * p + 1], alo, b4 + 2);
        }
#pragma unroll
        for (int p = 0; p < 4; p++) {
            int ntx = nh * 8 + 2 * p + nadd;
            uint32_t b4[4];
            ldsm_x4_t(b4, base + 32768u + (uint32_t)((ntx ^ sxr) << 4)); // W_lo
            mma16816(c[2 * p],     ahi, b4);
            mma16816(c[2 * p + 1], ahi, b4 + 2);
        }
    }
}

// GN(+relu) epilogue: stats -> barrier (+ issue async W prefetch) -> write Aex
// -> wait prefetch -> barrier.
template <bool GATHER>
__device__ __forceinline__ void ep_gn(float c[8][4],
                                      const float* __restrict__ gamma,
                                      const float* __restrict__ beta,
                                      uint32_t sb, char* smem,
                                      const int* hi_s, const int* wi_s,
                                      int rg, int nh, int l, int tid, int next_w) {
    const int q = l & 3;
    const int rA = rg * 16 + (l >> 2);
    const int rB = rA + 8;
    const int cb = nh * 64;

    if (GATHER) {
        const float* qA = g_qb   + hi_s[rA] * D + cb;
        const float* qB = g_qb   + hi_s[rB] * D + cb;
        const float* cA = g_ctxc + wi_s[rA] * D + cb;
        const float* cB = g_ctxc + wi_s[rB] * D + cb;
#pragma unroll
        for (int t = 0; t < 8; t++) {
            int c0 = t * 8 + q * 2;
            float2 a1 = __ldg((const float2*)(qA + c0));
            float2 a2 = __ldg((const float2*)(cA + c0));
            float2 b1 = __ldg((const float2*)(qB + c0));
            float2 b2 = __ldg((const float2*)(cB + c0));
            c[t][0] += a1.x + a2.x;  c[t][1] += a1.y + a2.y;
            c[t][2] += b1.x + b2.x;  c[t][3] += b1.y + b2.y;
        }
    }
    float sA = 0.f, qsA = 0.f, sB = 0.f, qsB = 0.f;
#pragma unroll
    for (int t = 0; t < 8; t++) {
        sA += c[t][0] + c[t][1];
        qsA = fmaf(c[t][0], c[t][0], fmaf(c[t][1], c[t][1], qsA));
        sB += c[t][2] + c[t][3];
        qsB = fmaf(c[t][2], c[t][2], fmaf(c[t][3], c[t][3], qsB));
    }
    sA  += __shfl_xor_sync(~0u, sA, 1);  sA  += __shfl_xor_sync(~0u, sA, 2);
    qsA += __shfl_xor_sync(~0u, qsA, 1); qsA += __shfl_xor_sync(~0u, qsA, 2);
    sB  += __shfl_xor_sync(~0u, sB, 1);  sB  += __shfl_xor_sync(~0u, sB, 2);
    qsB += __shfl_xor_sync(~0u, qsB, 1); qsB += __shfl_xor_sync(~0u, qsB, 2);

    float* st = (float*)(smem + SM_STATS);   // [half][sum(64) | sq(64)]
    if (q == 0) {
        st[nh * 128 + rA]      = sA;  st[nh * 128 + 64 + rA] = qsA;
        st[nh * 128 + rB]      = sB;  st[nh * 128 + 64 + rB] = qsB;
    }
    __syncthreads();   // stats visible; all W + Aex reads of this stage done

    copy_w_async(next_w, sb, tid);   // overlaps the normalize/pack below

    float S   = st[rA] + st[128 + rA];
    float SQ  = st[64 + rA] + st[192 + rA];
    float Sb  = st[rB] + st[128 + rB];
    float SQb = st[64 + rB] + st[192 + rB];
    float mA = S  * (1.f / 128.f), vA = SQ  * (1.f / 128.f) - mA * mA, rsA = rsqrtf(vA + EPS);
    float mB = Sb * (1.f / 128.f), vB = SQb * (1.f / 128.f) - mB * mB, rsB = rsqrtf(vB + EPS);

    int row, gsel;
    aex_lane(rg, l, row, gsel);
#pragma unroll
    for (int u = 0; u < 4; u++) {
        uint32_t dhi[4], dlo[4];
#pragma unroll
        for (int tt = 0; tt < 2; tt++) {
            int t = 2 * u + tt;
            int c0 = cb + t * 8 + q * 2;
            float g0 = __ldg(gamma + c0), g1 = __ldg(gamma + c0 + 1);
            float b0 = __ldg(beta + c0),  b1 = __ldg(beta + c0 + 1);
            float xA0 = fmaxf(fmaf((c[t][0] - mA) * rsA, g0, b0), 0.f);
            float xA1 = fmaxf(fmaf((c[t][1] - mA) * rsA, g1, b1), 0.f);
            float xB0 = fmaxf(fmaf((c[t][2] - mB) * rsB, g0, b0), 0.f);
            float xB1 = fmaxf(fmaf((c[t][3] - mB) * rsB, g1, b1), 0.f);
            split_pack(xA0, xA1, dhi[tt * 2],     dlo[tt * 2]);
            split_pack(xB0, xB1, dhi[tt * 2 + 1], dlo[tt * 2 + 1]);
        }
        int kc = nh * 4 + u;
        int g = 2 * kc + gsel;
        stsm_x4(aex_addr(sb, 0, row, g), dhi);
        stsm_x4(aex_addr(sb, 1, row, g), dlo);
    }
    cp_wait0();
    __syncthreads();   // Aex + next W visible
}

__global__ __launch_bounds__(256, 2) void k_edge_mma(
    const float* __restrict__ agt_ctrs, const float* __restrict__ ctx_ctrs,
    const int* __restrict__ hi, const int* __restrict__ wi,
    const float* __restrict__ dist_w1, const float* __restrict__ dist_b1,
    const float* __restrict__ dist_g2, const float* __restrict__ dist_b2,
    const float* __restrict__ ctx_g1, const float* __restrict__ ctx_b1) {
    extern __shared__ char smem[];
    const uint32_t sb = smem_u32(smem);
    const int tid = threadIdx.x;
    const int w = tid >> 5, l = tid & 31, q = l & 3;
    const int rg = w >> 1, nh = w & 1;         // row group 0-3, col half 0-1
    const int rA = rg * 16 + (l >> 2);
    const int rB = rA + 8;

    copy_w_async(0, sb, tid);                  // W0 in flight

    int* hi_s = (int*)(smem + SM_HIS);
    int* wi_s = (int*)(smem + SM_WIS);
    float2* d2s = (float2*)(smem + SM_D2);
    const int e0 = blockIdx.x * TRE;
    if (tid < TRE) {
        int h = hi[e0 + tid], ww = wi[e0 + tid];
        hi_s[tid] = h; wi_s[tid] = ww;
        float2 ac = ((const float2*)agt_ctrs)[h];
        float2 cc = ((const float2*)ctx_ctrs)[ww];
        d2s[tid] = make_float2(ac.x - cc.x, ac.y - cc.y);
    }
    __syncthreads();                           // ids/d2 visible

    // initial A = relu(d2 @ dist_w1 + b1), straight into Aex (each warp: 4 kc)
    {
        float2 ddA = d2s[rA], ddB = d2s[rB];
        int row, gsel;
        aex_lane(rg, l, row, gsel);
#pragma unroll
        for (int u = 0; u < 4; u++) {
            int kc = nh * 4 + u;
            uint32_t dhi[4], dlo[4];
#pragma unroll
            for (int tt = 0; tt < 2; tt++) {
                int col = kc * 16 + tt * 8 + q * 2;
                float w00 = __ldg(dist_w1 + col),     w01 = __ldg(dist_w1 + col + 1);
                float w10 = __ldg(dist_w1 + D + col), w11 = __ldg(dist_w1 + D + col + 1);
                float bb0 = __ldg(dist_b1 + col),     bb1 = __ldg(dist_b1 + col + 1);
                float xA0 = fmaxf(fmaf(ddA.x, w00, fmaf(ddA.y, w10, bb0)), 0.f);
                float xA1 = fmaxf(fmaf(ddA.x, w01, fmaf(ddA.y, w11, bb1)), 0.f);
                float xB0 = fmaxf(fmaf(ddB.x, w00, fmaf(ddB.y, w10, bb0)), 0.f);
                float xB1 = fmaxf(fmaf(ddB.x, w01, fmaf(ddB.y, w11, bb1)), 0.f);
                split_pack(xA0, xA1, dhi[tt * 2],     dlo[tt * 2]);
                split_pack(xB0, xB1, dhi[tt * 2 + 1], dlo[tt * 2 + 1]);
            }
            int g = 2 * kc + gsel;
            stsm_x4(aex_addr(sb, 0, row, g), dhi);
            stsm_x4(aex_addr(sb, 1, row, g), dlo);
        }
    }
    cp_wait0();
    __syncthreads();                           // Aex + W0 visible

    float c[8][4];
    // ---- stage 1: @ dist_w2, GN(dist_g2,b2)+relu ----
#pragma unroll
    for (int t = 0; t < 8; t++) { c[t][0] = c[t][1] = c[t][2] = c[t][3] = 0.f; }
    mma_stage(c, sb, rg, nh, l);
    ep_gn<false>(c, dist_g2, dist_b2, sb, smem, hi_s, wi_s, rg, nh, l, tid, 1);

    // ---- stage 2: @ ctx_w1[0:128] + qb[hi] + ctxc[wi], GN(ctx_g1,b1)+relu ----
#pragma unroll
    for (int t = 0; t < 8; t++) { c[t][0] = c[t][1] = c[t][2] = c[t][3] = 0.f; }
    mma_stage(c, sb, rg, nh, l);
    ep_gn<true>(c, ctx_g1, ctx_b1, sb, smem, hi_s, wi_s, rg, nh, l, tid, 2);

    // ---- stage 3: @ ctx_w2, scatter-add ----
#pragma unroll
    for (int t = 0; t < 8; t++) { c[t][0] = c[t][1] = c[t][2] = c[t][3] = 0.f; }
    mma_stage(c, sb, rg, nh, l);
    {
        float* baseA = g_acc + hi_s[rA] * D + nh * 64;
        float* baseB = g_acc + hi_s[rB] * D + nh * 64;
        const bool even = (q & 1) == 0;
#pragma unroll
        for (int t = 0; t < 8; t++) {
            float x0 = __shfl_xor_sync(~0u, c[t][0], 1);
            float x1 = __shfl_xor_sync(~0u, c[t][1], 1);
            float x2 = __shfl_xor_sync(~0u, c[t][2], 1);
            float x3 = __shfl_xor_sync(~0u, c[t][3], 1);
            if (even) red4(baseA + t * 8 + q * 2,       c[t][0], c[t][1], x0, x1);
            else      red4(baseB + t * 8 + (q - 1) * 2, x2, x3, c[t][2], c[t][3]);
        }
    }
}

// ---------------------------------------------------------------------------
// FFMA node kernels (known good)
// ---------------------------------------------------------------------------
__device__ __forceinline__ void gemm_tile(const float* in_s, const float* __restrict__ W,
                                          float* wbuf, float acc[8][4], int e0, int c4, int tid) {
    const float4* Wg = reinterpret_cast<const float4*>(W);
    float4* wb = reinterpret_cast<float4*>(wbuf);
    for (int kb = 0; kb < D; kb += KC) {
        __syncthreads();
        wb[tid]      = Wg[kb * (D / 4) + tid];
        wb[tid + NT] = Wg[kb * (D / 4) + tid + NT];
        __syncthreads();
#pragma unroll
        for (int kk = 0; kk < KC; kk++) {
            float4 w = wb[kk * (D / 4) + c4];
#pragma unroll
            for (int i = 0; i < 8; i++) {
                float h = in_s[(e0 + i) * D + kb + kk];
                acc[i][0] = fmaf(h, w.x, acc[i][0]);
                acc[i][1] = fmaf(h, w.y, acc[i][1]);
                acc[i][2] = fmaf(h, w.z, acc[i][2]);
                acc[i][3] = fmaf(h, w.w, acc[i][3]);
            }
        }
    }
}

__device__ __forceinline__ void zero_acc(float acc[8][4]) {
#pragma unroll
    for (int i = 0; i < 8; i++)
#pragma unroll
        for (int j = 0; j < 4; j++) acc[i][j] = 0.f;
}

__device__ __forceinline__ void store_acc(float* io, const float acc[8][4], int e0, int c4) {
#pragma unroll
    for (int i = 0; i < 8; i++) {
        float4 v = make_float4(acc[i][0], acc[i][1], acc[i][2], acc[i][3]);
        *reinterpret_cast<float4*>(&io[(e0 + i) * D + c4 * 4]) = v;
    }
}

__device__ __forceinline__ void gn_rows(float* io, const float* __restrict__ g,
                                        const float* __restrict__ b, bool do_relu, int tid) {
    int lane = tid & 31, w = tid >> 5;
    for (int r = w; r < TR; r += 8) {
        float v[4], s = 0.f, sq = 0.f;
#pragma unroll
        for (int j = 0; j < 4; j++) {
            v[j] = io[r * D + lane + 32 * j];
            s += v[j]; sq += v[j] * v[j];
        }
#pragma unroll
        for (int o = 16; o > 0; o >>= 1) {
            s  += __shfl_xor_sync(0xffffffffu, s, o);
            sq += __shfl_xor_sync(0xffffffffu, sq, o);
        }
        float mean = s * (1.f / D);
        float var  = sq * (1.f / D) - mean * mean;
        float rstd = rsqrtf(var + EPS);
#pragma unroll
        for (int j = 0; j < 4; j++) {
            int c = lane + 32 * j;
            float x = (v[j] - mean) * rstd * g[c] + b[c];
            io[r * D + c] = do_relu ? fmaxf(x, 0.f) : x;
        }
    }
}

__global__ __launch_bounds__(NT) void k_qb(const float* __restrict__ agts,
                                           const float* __restrict__ query_w,
                                           const float* __restrict__ query_g,
                                           const float* __restrict__ query_b,
                                           const float* __restrict__ ctx_w1) {
    __shared__ float io[TR * D];
    __shared__ float wbuf[KC * D];
    int tid = threadIdx.x;
    int r0 = blockIdx.x * TR;
    int lane = tid & 31, wid = tid >> 5;
    int c4 = lane, e0 = wid * 8;

    for (int idx = tid; idx < TR * D; idx += NT) io[idx] = agts[r0 * D + idx];

    float acc[8][4];
    zero_acc(acc);
    gemm_tile(io, query_w, wbuf, acc, e0, c4, tid);
    __syncthreads();
    store_acc(io, acc, e0, c4);
    __syncthreads();
    gn_rows(io, query_g, query_b, true, tid);
    __syncthreads();

    zero_acc(acc);
    gemm_tile(io, ctx_w1 + D * D, wbuf, acc, e0, c4, tid);
#pragma unroll
    for (int i = 0; i < 8; i++) {
        float4 v = make_float4(acc[i][0], acc[i][1], acc[i][2], acc[i][3]);
        *reinterpret_cast<float4*>(&g_qb[(r0 + e0 + i) * D + c4 * 4]) = v;
    }
}

__global__ __launch_bounds__(NT) void k_accinit(const float* __restrict__ agts,
                                                const float* __restrict__ agt_w) {
    __shared__ float io[TR * D];
    __shared__ float wbuf[KC * D];
    int tid = threadIdx.x;
    int r0 = blockIdx.x * TR;
    int lane = tid & 31, wid = tid >> 5;
    int c4 = lane, e0 = wid * 8;

    for (int idx = tid; idx < TR * D; idx += NT) io[idx] = agts[r0 * D + idx];

    float acc[8][4];
    zero_acc(acc);
    gemm_tile(io, agt_w, wbuf, acc, e0, c4, tid);
#pragma unroll
    for (int i = 0; i < 8; i++) {
        float4 v = make_float4(acc[i][0], acc[i][1], acc[i][2], acc[i][3]);
        *reinterpret_cast<float4*>(&g_acc[(r0 + e0 + i) * D + c4 * 4]) = v;
    }
}

__global__ __launch_bounds__(NT) void k_ctxc(const float* __restrict__ ctx,
                                             const float* __restrict__ ctx_w1) {
    __shared__ float io[TR * D];
    __shared__ float wbuf[KC * D];
    int tid = threadIdx.x;
    int r0 = blockIdx.x * TR;
    int lane = tid & 31, wid = tid >> 5;
    int c4 = lane, e0 = wid * 8;

    for (int idx = tid; idx < TR * D; idx += NT) io[idx] = ctx[r0 * D + idx];

    float acc[8][4];
    zero_acc(acc);
    gemm_tile(io, ctx_w1 + 2 * D * D, wbuf, acc, e0, c4, tid);
#pragma unroll
    for (int i = 0; i < 8; i++) {
        float4 v = make_float4(acc[i][0], acc[i][1], acc[i][2], acc[i][3]);
        *reinterpret_cast<float4*>(&g_ctxc[(r0 + e0 + i) * D + c4 * 4]) = v;
    }
}

__global__ __launch_bounds__(NT) void k_final(const float* __restrict__ agts,
                                              const float* __restrict__ norm_g,
                                              const float* __restrict__ norm_b,
                                              const float* __restrict__ lin_w,
                                              const float* __restrict__ lin_g,
                                              const float* __restrict__ lin_b,
                                              float* __restrict__ out) {
    __shared__ float io[TR * D];
    __shared__ float wbuf[KC * D];
    int tid = threadIdx.x;
    int r0 = blockIdx.x * TR;
    int lane = tid & 31, wid = tid >> 5;
    int c4 = lane, e0 = wid * 8;

    for (int idx = tid; idx < TR * D; idx += NT) io[idx] = g_acc[r0 * D + idx];
    __syncthreads();
    gn_rows(io, norm_g, norm_b, true, tid);
    __syncthreads();

    float acc[8][4];
    zero_acc(acc);
    gemm_tile(io, lin_w, wbuf, acc, e0, c4, tid);
    __syncthreads();
    store_acc(io, acc, e0, c4);
    __syncthreads();

    for (int r = wid; r < TR; r += 8) {
        float v[4], s = 0.f, sq = 0.f;
#pragma unroll
        for (int j = 0; j < 4; j++) {
            v[j] = io[r * D + lane + 32 * j];
            s += v[j]; sq += v[j] * v[j];
        }
#pragma unroll
        for (int o = 16; o > 0; o >>= 1) {
            s  += __shfl_xor_sync(0xffffffffu, s, o);
            sq += __shfl_xor_sync(0xffffffffu, sq, o);
        }
        float mean = s * (1.f / D);
        float var  = sq * (1.f / D) - mean * mean;
        float rstd = rsqrtf(var + EPS);
#pragma unroll
        for (int j = 0; j < 4; j++) {
            int c = lane + 32 * j;
            float x = (v[j] - mean) * rstd * lin_g[c] + lin_b[c];
            float res = agts[(r0 + r) * D + c];
            out[(r0 + r) * D + c] = fmaxf(x + res, 0.f);
        }
    }
}

// ---------------------------------------------------------------------------
extern "C" void kernel_launch(void* const* d_in, const int* in_sizes, int n_in,
                              void* d_out, int out_size) {
    const float* agts     = (const float*)d_in[0];
    const float* ctx      = (const float*)d_in[1];
    const float* agt_ctrs = (const float*)d_in[2];
    const float* ctx_ctrs = (const float*)d_in[3];
    const int*   hi       = (const int*)d_in[4];
    const int*   wi       = (const int*)d_in[5];
    const float* dist_w1  = (const float*)d_in[6];
    const float* dist_b1  = (const float*)d_in[7];
    const float* dist_w2  = (const float*)d_in[8];
    const float* dist_g2  = (const float*)d_in[9];
    const float* dist_b2  = (const float*)d_in[10];
    const float* query_w  = (const float*)d_in[11];
    const float* query_g  = (const float*)d_in[12];
    const float* query_b  = (const float*)d_in[13];
    const float* ctx_w1   = (const float*)d_in[14];
    const float* ctx_g1   = (const float*)d_in[15];
    const float* ctx_b1   = (const float*)d_in[16];
    const float* ctx_w2   = (const float*)d_in[17];
    const float* agt_w    = (const float*)d_in[18];
    const float* norm_g   = (const float*)d_in[19];
    const float* norm_b   = (const float*)d_in[20];
    const float* lin_w    = (const float*)d_in[21];
    const float* lin_g    = (const float*)d_in[22];
    const float* lin_b    = (const float*)d_in[23];
    float* out = (float*)d_out;

    cudaFuncSetAttribute(k_edge_mma, cudaFuncAttributeMaxDynamicSharedMemorySize, SMEM_EDGE);

    k_prep<<<dim3(16, 3), 256>>>(dist_w2, ctx_w1, ctx_w2);
    k_qb<<<NA / TR, NT>>>(agts, query_w, query_g, query_b, ctx_w1);
    k_accinit<<<NA / TR, NT>>>(agts, agt_w);
    k_ctxc<<<NC / TR, NT>>>(ctx, ctx_w1);
    k_edge_mma<<<NE / TRE, 256, SMEM_EDGE>>>(agt_ctrs, ctx_ctrs, hi, wi,
                                             dist_w1, dist_b1,
                                             dist_g2, dist_b2,
                                             ctx_g1, ctx_b1);
    k_final<<<NA / TR, NT>>>(agts, norm_g, norm_b, lin_w, lin_g, lin_b, out);
}

// round 7
// speedup vs baseline: 1.1278x; 1.0030x over previous
#include <cuda_runtime.h>
#include <cuda_bf16.h>
#include <cstdint>

#define D     128
#define NA    16384
#define NC    16384
#define NE    524288
#define TR    64
#define NT    256
#define KC    16
#define TRE   64      // edges per block (4 row-groups x 2 col-halves = 8 warps)
#define EPS   1e-5f
#define AROW  132     // floats per Aex row (bank-conflict-free stride)

// ---------------------------------------------------------------------------
// device scratch (no allocation)
// ---------------------------------------------------------------------------
__device__ __align__(16) float g_qb[NA * D];      // relu(GN(agts@query_w)) @ ctx_w1[128:256]
__device__ __align__(16) float g_ctxc[NC * D];    // ctx @ ctx_w1[256:384]
__device__ __align__(16) float g_acc[NA * D];     // agts@agt_w + scattered edge output
__device__ __align__(16) uint32_t g_wt[3 * 16384];// tf32 W images, [k][n] swizzled

// ---------------------------------------------------------------------------
// helpers
// ---------------------------------------------------------------------------
__device__ __forceinline__ uint32_t smem_u32(const void* p) {
    uint32_t a;
    asm("{ .reg .u64 t; cvta.to.shared.u64 t, %1; cvt.u32.u64 %0, t; }" : "=r"(a) : "l"(p));
    return a;
}

__device__ __forceinline__ uint32_t f2tf(float x) {
    uint32_t u;
    asm("cvt.rna.tf32.f32 %0, %1;" : "=r"(u) : "f"(x));
    return u;
}

__device__ __forceinline__ void mma_tf32(float c[4], const uint32_t a[4], uint32_t b0, uint32_t b1) {
    asm volatile(
        "mma.sync.aligned.m16n8k8.row.col.f32.tf32.tf32.f32 "
        "{%0,%1,%2,%3}, {%4,%5,%6,%7}, {%8,%9}, {%0,%1,%2,%3};"
        : "+f"(c[0]), "+f"(c[1]), "+f"(c[2]), "+f"(c[3])
        : "r"(a[0]), "r"(a[1]), "r"(a[2]), "r"(a[3]), "r"(b0), "r"(b1));
}

__device__ __forceinline__ uint32_t lds32(uint32_t a) {
    uint32_t v;
    asm volatile("ld.shared.b32 %0, [%1];" : "=r"(v) : "r"(a));
    return v;
}
__device__ __forceinline__ void sts64(uint32_t a, uint32_t x, uint32_t y) {
    asm volatile("st.shared.v2.b32 [%0], {%1, %2};" :: "r"(a), "r"(x), "r"(y) : "memory");
}

__device__ __forceinline__ void red4(float* p, float a, float b, float c, float d) {
    asm volatile("red.global.add.v4.f32 [%0], {%1,%2,%3,%4};"
                 :: "l"(p), "f"(a), "f"(b), "f"(c), "f"(d) : "memory");
}

__device__ __forceinline__ void cp16(uint32_t daddr, const void* g) {
    asm volatile("cp.async.cg.shared.global [%0], [%1], 16;" :: "r"(daddr), "l"(g) : "memory");
}
__device__ __forceinline__ void cp_commit() { asm volatile("cp.async.commit_group;" ::: "memory"); }
__device__ __forceinline__ void cp_wait0()  { asm volatile("cp.async.wait_group 0;" ::: "memory"); }

// ---------------------------------------------------------------------------
// k_edge smem map (bytes)
// ---------------------------------------------------------------------------
#define SM_W      0        /* 64KB tf32 W image */
#define SM_AEX    65536    /* 64 rows x AROW floats = 33792B */
#define SM_STATS  99328    /* 256 floats */
#define SM_HIS    100352
#define SM_WIS    100608
#define SM_D2     100864
#define SMEM_EDGE 101376

// W image: element (k,n) at k*128 + ((n>>3 ^ (k&3))<<3) + (n&7)  (uint32 index)
__global__ void k_prep(const float* __restrict__ w0, const float* __restrict__ w1,
                       const float* __restrict__ w2) {
    int m = blockIdx.y;
    const float* src = (m == 0) ? w0 : (m == 1 ? w1 : w2);
    int idx = blockIdx.x * 256 + threadIdx.x;    // k*128 + n
    int k = idx >> 7, n = idx & 127;
    int s = k * 128 + ((((n >> 3) ^ (k & 3)) << 3) | (n & 7));
    g_wt[m * 16384 + s] = f2tf(src[idx]);
}

// async copy W image m into smem (64KB: 16 x 16B per thread)
__device__ __forceinline__ void copy_w_async(int m, uint32_t sb, int tid) {
    const uint4* s4 = (const uint4*)(g_wt + m * 16384);
#pragma unroll
    for (int i = 0; i < 16; i++)
        cp16(sb + SM_W + (uint32_t)((i * 256 + tid) * 16), s4 + i * 256 + tid);
    cp_commit();
}

// C[8 tiles][4] += A[16 rows] @ W, tf32 single product; warp covers cols nh*64..+63
__device__ __forceinline__ void mma_stage(float c[8][4], uint32_t sb, int rg, int nh, int l) {
    const int ar = l >> 2, ak = l & 3;           // A-frag lane coords
    const int bk = l & 3, bn = l >> 2;           // B-frag lane coords
    const uint32_t abase = sb + SM_AEX + (uint32_t)((rg * 16 + ar) * AROW * 4 + ak * 4);
    const uint32_t bbase = sb + SM_W + (uint32_t)(bk * 512 + bn * 4);
#pragma unroll
    for (int kc = 0; kc < 16; kc++) {
        uint32_t a[4];
        uint32_t aa = abase + (uint32_t)(kc * 32);
        a[0] = lds32(aa);
        a[2] = lds32(aa + 16);
        a[1] = lds32(aa + 8 * AROW * 4);
        a[3] = lds32(aa + 8 * AROW * 4 + 16);
        uint32_t bb = bbase + (uint32_t)(kc * 4096);
#pragma unroll
        for (int p = 0; p < 8; p++) {
            int ntile = nh * 8 + p;
            uint32_t boff = bb + (uint32_t)(((ntile ^ bk) * 8) * 4);
            uint32_t b0 = lds32(boff);
            uint32_t b1 = lds32(boff + 2048);
            mma_tf32(c[p], a, b0, b1);
        }
    }
}

// GN(+relu) epilogue: stats -> barrier (+W prefetch) -> normalize -> Aex(tf32) -> barrier
template <bool GATHER>
__device__ __forceinline__ void ep_gn(float c[8][4],
                                      const float* __restrict__ gamma,
                                      const float* __restrict__ beta,
                                      uint32_t sb, char* smem,
                                      const int* hi_s, const int* wi_s,
                                      const float2* pq, const float2* pc,
                                      int rg, int nh, int l, int tid, int next_w) {
    const int q = l & 3;
    const int rA = rg * 16 + (l >> 2);
    const int rB = rA + 8;
    const int cb = nh * 64;

    if (GATHER) {
        // rA terms were prefetched into pq/pc before the mma; load rB fresh
        const float* qB = g_qb   + hi_s[rB] * D + cb;
        const float* cB = g_ctxc + wi_s[rB] * D + cb;
#pragma unroll
        for (int t = 0; t < 8; t++) {
            float2 b1 = __ldg((const float2*)(qB + t * 8) + q);
            float2 b2 = __ldg((const float2*)(cB + t * 8) + q);
            c[t][0] += pq[t].x + pc[t].x;
            c[t][1] += pq[t].y + pc[t].y;
            c[t][2] += b1.x + b2.x;
            c[t][3] += b1.y + b2.y;
        }
    }
    float sA = 0.f, qsA = 0.f, sB = 0.f, qsB = 0.f;
#pragma unroll
    for (int t = 0; t < 8; t++) {
        sA += c[t][0] + c[t][1];
        qsA = fmaf(c[t][0], c[t][0], fmaf(c[t][1], c[t][1], qsA));
        sB += c[t][2] + c[t][3];
        qsB = fmaf(c[t][2], c[t][2], fmaf(c[t][3], c[t][3], qsB));
    }
    sA  += __shfl_xor_sync(~0u, sA, 1);  sA  += __shfl_xor_sync(~0u, sA, 2);
    qsA += __shfl_xor_sync(~0u, qsA, 1); qsA += __shfl_xor_sync(~0u, qsA, 2);
    sB  += __shfl_xor_sync(~0u, sB, 1);  sB  += __shfl_xor_sync(~0u, sB, 2);
    qsB += __shfl_xor_sync(~0u, qsB, 1); qsB += __shfl_xor_sync(~0u, qsB, 2);

    float* st = (float*)(smem + SM_STATS);   // [half][sum(64) | sq(64)]
    if (q == 0) {
        st[nh * 128 + rA]      = sA;  st[nh * 128 + 64 + rA] = qsA;
        st[nh * 128 + rB]      = sB;  st[nh * 128 + 64 + rB] = qsB;
    }
    __syncthreads();   // stats visible; all W reads of this stage done

    if (next_w >= 0) copy_w_async(next_w, sb, tid);   // overlaps normalize below

    float S   = st[rA] + st[128 + rA];
    float SQ  = st[64 + rA] + st[192 + rA];
    float Sb  = st[rB] + st[128 + rB];
    float SQb = st[64 + rB] + st[192 + rB];
    float mA = S  * (1.f / 128.f), vA = SQ  * (1.f / 128.f) - mA * mA, rsA = rsqrtf(vA + EPS);
    float mB = Sb * (1.f / 128.f), vB = SQb * (1.f / 128.f) - mB * mB, rsB = rsqrtf(vB + EPS);

#pragma unroll
    for (int t = 0; t < 8; t++) {
        int c0 = cb + t * 8 + q * 2;
        float g0 = __ldg(gamma + c0), g1 = __ldg(gamma + c0 + 1);
        float b0 = __ldg(beta + c0),  b1 = __ldg(beta + c0 + 1);
        float xA0 = fmaxf(fmaf((c[t][0] - mA) * rsA, g0, b0), 0.f);
        float xA1 = fmaxf(fmaf((c[t][1] - mA) * rsA, g1, b1), 0.f);
        float xB0 = fmaxf(fmaf((c[t][2] - mB) * rsB, g0, b0), 0.f);
        float xB1 = fmaxf(fmaf((c[t][3] - mB) * rsB, g1, b1), 0.f);
        sts64(sb + SM_AEX + (uint32_t)(rA * AROW * 4 + c0 * 4), f2tf(xA0), f2tf(xA1));
        sts64(sb + SM_AEX + (uint32_t)(rB * AROW * 4 + c0 * 4), f2tf(xB0), f2tf(xB1));
    }
    cp_wait0();
    __syncthreads();   // Aex + next W visible
}

__global__ __launch_bounds__(256, 2) void k_edge_mma(
    const float* __restrict__ agt_ctrs, const float* __restrict__ ctx_ctrs,
    const int* __restrict__ hi, const int* __restrict__ wi,
    const float* __restrict__ dist_w1, const float* __restrict__ dist_b1,
    const float* __restrict__ dist_g2, const float* __restrict__ dist_b2,
    const float* __restrict__ ctx_g1, const float* __restrict__ ctx_b1) {
    extern __shared__ char smem[];
    const uint32_t sb = smem_u32(smem);
    const int tid = threadIdx.x;
    const int w = tid >> 5, l = tid & 31, q = l & 3;
    const int rg = w >> 1, nh = w & 1;         // row group 0-3, col half 0-1
    const int rA = rg * 16 + (l >> 2);
    const int rB = rA + 8;

    copy_w_async(0, sb, tid);                  // W0 in flight

    int* hi_s = (int*)(smem + SM_HIS);
    int* wi_s = (int*)(smem + SM_WIS);
    float2* d2s = (float2*)(smem + SM_D2);
    const int e0 = blockIdx.x * TRE;
    if (tid < TRE) {
        int h = hi[e0 + tid], ww = wi[e0 + tid];
        hi_s[tid] = h; wi_s[tid] = ww;
        float2 ac = ((const float2*)agt_ctrs)[h];
        float2 cc = ((const float2*)ctx_ctrs)[ww];
        d2s[tid] = make_float2(ac.x - cc.x, ac.y - cc.y);
    }
    __syncthreads();                           // ids/d2 visible

    // initial A = relu(d2 @ dist_w1 + b1) -> Aex as tf32
    for (int idx = tid; idx < TRE * D; idx += 256) {
        int row = idx >> 7, col = idx & 127;
        float2 dd = d2s[row];
        float x = fmaxf(fmaf(dd.x, __ldg(dist_w1 + col),
                     fmaf(dd.y, __ldg(dist_w1 + D + col), __ldg(dist_b1 + col))), 0.f);
        *(uint32_t*)(smem + SM_AEX + row * AROW * 4 + col * 4) = f2tf(x);
    }
    cp_wait0();
    __syncthreads();                           // Aex + W0 visible

    float c[8][4];
    // ---- stage 1: @ dist_w2, GN(dist_g2,b2)+relu ----
#pragma unroll
    for (int t = 0; t < 8; t++) { c[t][0] = c[t][1] = c[t][2] = c[t][3] = 0.f; }
    mma_stage(c, sb, rg, nh, l);
    ep_gn<false>(c, dist_g2, dist_b2, sb, smem, hi_s, wi_s, nullptr, nullptr, rg, nh, l, tid, 1);

    // ---- stage 2: @ ctx_w1[0:128] + qb[hi] + ctxc[wi], GN(ctx_g1,b1)+relu ----
    float2 pq[8], pc[8];
    {
        const int cb = nh * 64;
        const float* qA = g_qb   + hi_s[rA] * D + cb;
        const float* cA = g_ctxc + wi_s[rA] * D + cb;
#pragma unroll
        for (int t = 0; t < 8; t++) {
            pq[t] = __ldg((const float2*)(qA + t * 8) + q);
            pc[t] = __ldg((const float2*)(cA + t * 8) + q);
        }
    }
#pragma unroll
    for (int t = 0; t < 8; t++) { c[t][0] = c[t][1] = c[t][2] = c[t][3] = 0.f; }
    mma_stage(c, sb, rg, nh, l);
    ep_gn<true>(c, ctx_g1, ctx_b1, sb, smem, hi_s, wi_s, pq, pc, rg, nh, l, tid, 2);

    // ---- stage 3: @ ctx_w2, scatter-add ----
#pragma unroll
    for (int t = 0; t < 8; t++) { c[t][0] = c[t][1] = c[t][2] = c[t][3] = 0.f; }
    mma_stage(c, sb, rg, nh, l);
    {
        float* baseA = g_acc + hi_s[rA] * D + nh * 64;
        float* baseB = g_acc + hi_s[rB] * D + nh * 64;
        const bool even = (q & 1) == 0;
#pragma unroll
        for (int t = 0; t < 8; t++) {
            float x0 = __shfl_xor_sync(~0u, c[t][0], 1);
            float x1 = __shfl_xor_sync(~0u, c[t][1], 1);
            float x2 = __shfl_xor_sync(~0u, c[t][2], 1);
            float x3 = __shfl_xor_sync(~0u, c[t][3], 1);
            if (even) red4(baseA + t * 8 + q * 2,       c[t][0], c[t][1], x0, x1);
            else      red4(baseB + t * 8 + (q - 1) * 2, x2, x3, c[t][2], c[t][3]);
        }
    }
}

// ---------------------------------------------------------------------------
// FFMA node kernels (merged)
// ---------------------------------------------------------------------------
__device__ __forceinline__ void gemm_tile(const float* in_s, const float* __restrict__ W,
                                          float* wbuf, float acc[8][4], int e0, int c4, int tid) {
    const float4* Wg = reinterpret_cast<const float4*>(W);
    float4* wb = reinterpret_cast<float4*>(wbuf);
    for (int kb = 0; kb < D; kb += KC) {
        __syncthreads();
        wb[tid]      = Wg[kb * (D / 4) + tid];
        wb[tid + NT] = Wg[kb * (D / 4) + tid + NT];
        __syncthreads();
#pragma unroll
        for (int kk = 0; kk < KC; kk++) {
            float4 w = wb[kk * (D / 4) + c4];
#pragma unroll
            for (int i = 0; i < 8; i++) {
                float h = in_s[(e0 + i) * D + kb + kk];
                acc[i][0] = fmaf(h, w.x, acc[i][0]);
                acc[i][1] = fmaf(h, w.y, acc[i][1]);
                acc[i][2] = fmaf(h, w.z, acc[i][2]);
                acc[i][3] = fmaf(h, w.w, acc[i][3]);
            }
        }
    }
}

__device__ __forceinline__ void zero_acc(float acc[8][4]) {
#pragma unroll
    for (int i = 0; i < 8; i++)
#pragma unroll
        for (int j = 0; j < 4; j++) acc[i][j] = 0.f;
}

__device__ __forceinline__ void store_acc(float* io, const float acc[8][4], int e0, int c4) {
#pragma unroll
    for (int i = 0; i < 8; i++) {
        float4 v = make_float4(acc[i][0], acc[i][1], acc[i][2], acc[i][3]);
        *reinterpret_cast<float4*>(&io[(e0 + i) * D + c4 * 4]) = v;
    }
}

__device__ __forceinline__ void gn_rows(float* io, const float* __restrict__ g,
                                        const float* __restrict__ b, bool do_relu, int tid) {
    int lane = tid & 31, w = tid >> 5;
    for (int r = w; r < TR; r += 8) {
        float v[4], s = 0.f, sq = 0.f;
#pragma unroll
        for (int j = 0; j < 4; j++) {
            v[j] = io[r * D + lane + 32 * j];
            s += v[j]; sq += v[j] * v[j];
        }
#pragma unroll
        for (int o = 16; o > 0; o >>= 1) {
            s  += __shfl_xor_sync(0xffffffffu, s, o);
            sq += __shfl_xor_sync(0xffffffffu, sq, o);
        }
        float mean = s * (1.f / D);
        float var  = sq * (1.f / D) - mean * mean;
        float rstd = rsqrtf(var + EPS);
#pragma unroll
        for (int j = 0; j < 4; j++) {
            int c = lane + 32 * j;
            float x = (v[j] - mean) * rstd * g[c] + b[c];
            io[r * D + c] = do_relu ? fmaxf(x, 0.f) : x;
        }
    }
}

__global__ __launch_bounds__(NT) void k_nodes(const float* __restrict__ agts,
                                              const float* __restrict__ ctx,
                                              const float* __restrict__ query_w,
                                              const float* __restrict__ query_g,
                                              const float* __restrict__ query_b,
                                              const float* __restrict__ ctx_w1,
                                              const float* __restrict__ agt_w) {
    __shared__ float io[TR * D];
    __shared__ float wbuf[KC * D];
    int tid = threadIdx.x;
    int task = blockIdx.x >> 8;          // 0: qb, 1: accinit, 2: ctxc
    int r0 = (blockIdx.x & 255) * TR;
    int lane = tid & 31, wid = tid >> 5;
    int c4 = lane, e0 = wid * 8;
    float acc[8][4];

    if (task == 0) {
        for (int idx = tid; idx < TR * D; idx += NT) io[idx] = agts[r0 * D + idx];
        zero_acc(acc);
        gemm_tile(io, query_w, wbuf, acc, e0, c4, tid);
        __syncthreads();
        store_acc(io, acc, e0, c4);
        __syncthreads();
        gn_rows(io, query_g, query_b, true, tid);
        __syncthreads();
        zero_acc(acc);
        gemm_tile(io, ctx_w1 + D * D, wbuf, acc, e0, c4, tid);
#pragma unroll
        for (int i = 0; i < 8; i++) {
            float4 v = make_float4(acc[i][0], acc[i][1], acc[i][2], acc[i][3]);
            *reinterpret_cast<float4*>(&g_qb[(r0 + e0 + i) * D + c4 * 4]) = v;
        }
    } else if (task == 1) {
        for (int idx = tid; idx < TR * D; idx += NT) io[idx] = agts[r0 * D + idx];
        zero_acc(acc);
        gemm_tile(io, agt_w, wbuf, acc, e0, c4, tid);
#pragma unroll
        for (int i = 0; i < 8; i++) {
            float4 v = make_float4(acc[i][0], acc[i][1], acc[i][2], acc[i][3]);
            *reinterpret_cast<float4*>(&g_acc[(r0 + e0 + i) * D + c4 * 4]) = v;
        }
    } else {
        for (int idx = tid; idx < TR * D; idx += NT) io[idx] = ctx[r0 * D + idx];
        zero_acc(acc);
        gemm_tile(io, ctx_w1 + 2 * D * D, wbuf, acc, e0, c4, tid);
#pragma unroll
        for (int i = 0; i < 8; i++) {
            float4 v = make_float4(acc[i][0], acc[i][1], acc[i][2], acc[i][3]);
            *reinterpret_cast<float4*>(&g_ctxc[(r0 + e0 + i) * D + c4 * 4]) = v;
        }
    }
}

__global__ __launch_bounds__(NT) void k_final(const float* __restrict__ agts,
                                              const float* __restrict__ norm_g,
                                              const float* __restrict__ norm_b,
                                              const float* __restrict__ lin_w,
                                              const float* __restrict__ lin_g,
                                              const float* __restrict__ lin_b,
                                              float* __restrict__ out) {
    __shared__ float io[TR * D];
    __shared__ float wbuf[KC * D];
    int tid = threadIdx.x;
    int r0 = blockIdx.x * TR;
    int lane = tid & 31, wid = tid >> 5;
    int c4 = lane, e0 = wid * 8;

    for (int idx = tid; idx < TR * D; idx += NT) io[idx] = g_acc[r0 * D + idx];
    __syncthreads();
    gn_rows(io, norm_g, norm_b, true, tid);
    __syncthreads();

    float acc[8][4];
    zero_acc(acc);
    gemm_tile(io, lin_w, wbuf, acc, e0, c4, tid);
    __syncthreads();
    store_acc(io, acc, e0, c4);
    __syncthreads();

    for (int r = wid; r < TR; r += 8) {
        float v[4], s = 0.f, sq = 0.f;
#pragma unroll
        for (int j = 0; j < 4; j++) {
            v[j] = io[r * D + lane + 32 * j];
            s += v[j]; sq += v[j] * v[j];
        }
#pragma unroll
        for (int o = 16; o > 0; o >>= 1) {
            s  += __shfl_xor_sync(0xffffffffu, s, o);
            sq += __shfl_xor_sync(0xffffffffu, sq, o);
        }
        float mean = s * (1.f / D);
        float var  = sq * (1.f / D) - mean * mean;
        float rstd = rsqrtf(var + EPS);
#pragma unroll
        for (int j = 0; j < 4; j++) {
            int c = lane + 32 * j;
            float x = (v[j] - mean) * rstd * lin_g[c] + lin_b[c];
            float res = agts[(r0 + r) * D + c];
            out[(r0 + r) * D + c] = fmaxf(x + res, 0.f);
        }
    }
}

// ---------------------------------------------------------------------------
extern "C" void kernel_launch(void* const* d_in, const int* in_sizes, int n_in,
                              void* d_out, int out_size) {
    const float* agts     = (const float*)d_in[0];
    const float* ctx      = (const float*)d_in[1];
    const float* agt_ctrs = (const float*)d_in[2];
    const float* ctx_ctrs = (const float*)d_in[3];
    const int*   hi       = (const int*)d_in[4];
    const int*   wi       = (const int*)d_in[5];
    const float* dist_w1  = (const float*)d_in[6];
    const float* dist_b1  = (const float*)d_in[7];
    const float* dist_w2  = (const float*)d_in[8];
    const float* dist_g2  = (const float*)d_in[9];
    const float* dist_b2  = (const float*)d_in[10];
    const float* query_w  = (const float*)d_in[11];
    const float* query_g  = (const float*)d_in[12];
    const float* query_b  = (const float*)d_in[13];
    const float* ctx_w1   = (const float*)d_in[14];
    const float* ctx_g1   = (const float*)d_in[15];
    const float* ctx_b1   = (const float*)d_in[16];
    const float* ctx_w2   = (const float*)d_in[17];
    const float* agt_w    = (const float*)d_in[18];
    const float* norm_g   = (const float*)d_in[19];
    const float* norm_b   = (const float*)d_in[20];
    const float* lin_w    = (const float*)d_in[21];
    const float* lin_g    = (const float*)d_in[22];
    const float* lin_b    = (const float*)d_in[23];
    float* out = (float*)d_out;

    cudaFuncSetAttribute(k_edge_mma, cudaFuncAttributeMaxDynamicSharedMemorySize, SMEM_EDGE);

    k_prep<<<dim3(64, 3), 256>>>(dist_w2, ctx_w1, ctx_w2);
    k_nodes<<<768, NT>>>(agts, ctx, query_w, query_g, query_b, ctx_w1, agt_w);
    k_edge_mma<<<NE / TRE, 256, SMEM_EDGE>>>(agt_ctrs, ctx_ctrs, hi, wi,
                                             dist_w1, dist_b1,
                                             dist_g2, dist_b2,
                                             ctx_g1, ctx_b1);
    k_final<<<NA / TR, NT>>>(agts, norm_g, norm_b, lin_w, lin_g, lin_b, out);
}